// round 11
// baseline (speedup 1.0000x reference)
#include <cuda_runtime.h>
#include <cuda_bf16.h>
#include <cstdint>
#include <cstddef>

#define DEVI __device__ __forceinline__

namespace {
constexpr int BATCH = 16, SEQ = 512, DIM = 1024, NH = 16, HDIM = 64;
constexpr int MROWS = BATCH * SEQ;      // 8192
constexpr float ATT_SCALE = 0.125f;     // 1/sqrt(64)
constexpr int BM = 128, BN = 64, BK = 64;    // CTA tile 128x64, K-chunk 64 (128B row)
constexpr int KT = DIM / BK;                 // 16
constexpr int NST = 3;
constexpr int STAGE_BYTES = (BM + BN) * 128; // 24576 (A 16KB + B 8KB)
constexpr int GEMM_SMEM = NST * STAGE_BYTES + 256;   // 73984
}

// ---------------- scratch (device globals; no allocation allowed) ----------------
__device__ __nv_bfloat16 g_hb[MROWS * DIM];
__device__ __nv_bfloat16 g_cb[MROWS * DIM];
__device__ __nv_bfloat16 g_w5[5 * DIM * DIM];   // Wq,Wk,Wv,Wo,Wg packed
__device__ __nv_bfloat16 g_q[MROWS * DIM];
__device__ __nv_bfloat16 g_k[MROWS * DIM];
__device__ __nv_bfloat16 g_v[MROWS * DIM];
__device__ __nv_bfloat16 g_attn[MROWS * DIM];
__device__ __nv_bfloat16 g_gate[MROWS * DIM];
__device__ __nv_bfloat16 g_yo[MROWS * DIM];

// ---------------- small helpers ----------------
DEVI uint32_t pack_bf16(float a, float b) {
    __nv_bfloat162 t;
    t.x = __float2bfloat16(a);
    t.y = __float2bfloat16(b);
    return *reinterpret_cast<uint32_t*>(&t);
}
DEVI void mma16816(float* c, const uint32_t* a, const uint32_t* b) {
    asm volatile(
        "mma.sync.aligned.m16n8k16.row.col.f32.bf16.bf16.f32 "
        "{%0,%1,%2,%3}, {%4,%5,%6,%7}, {%8,%9}, {%0,%1,%2,%3};"
        : "+f"(c[0]), "+f"(c[1]), "+f"(c[2]), "+f"(c[3])
        : "r"(a[0]), "r"(a[1]), "r"(a[2]), "r"(a[3]), "r"(b[0]), "r"(b[1]));
}
DEVI void ldmx4(uint32_t* r, uint32_t addr) {
    asm volatile("ldmatrix.sync.aligned.m8n8.x4.shared.b16 {%0,%1,%2,%3}, [%4];"
                 : "=r"(r[0]), "=r"(r[1]), "=r"(r[2]), "=r"(r[3]) : "r"(addr));
}
DEVI void ldmx2(uint32_t* r, uint32_t addr) {
    asm volatile("ldmatrix.sync.aligned.m8n8.x2.shared.b16 {%0,%1}, [%2];"
                 : "=r"(r[0]), "=r"(r[1]) : "r"(addr));
}
DEVI void ldmx2t(uint32_t* r, uint32_t addr) {
    asm volatile("ldmatrix.sync.aligned.m8n8.x2.trans.shared.b16 {%0,%1}, [%2];"
                 : "=r"(r[0]), "=r"(r[1]) : "r"(addr));
}
DEVI void cpasync16(uint32_t dst, const void* src) {
    asm volatile("cp.async.cg.shared.global [%0], [%1], 16;" :: "r"(dst), "l"(src));
}
DEVI void cpasync16z(uint32_t dst, const void* src, int srcsize) {
    asm volatile("cp.async.cg.shared.global [%0], [%1], 16, %2;"
                 :: "r"(dst), "l"(src), "r"(srcsize));
}

// ---------------- fused fp32 -> bf16 conversion (activations + 5 weights) --------
__global__ void cvt_all_kernel(const float* __restrict__ hidden, const float* __restrict__ cross,
                               const float* __restrict__ wq, const float* __restrict__ wk,
                               const float* __restrict__ wv, const float* __restrict__ wo,
                               const float* __restrict__ wg) {
    constexpr int ACT = MROWS * DIM / 4;   // 2097152 vec4
    constexpr int WV  = DIM * DIM / 4;     // 262144 vec4 (2^18)
    constexpr int TOT = 2 * ACT + 5 * WV;
    const int stride = gridDim.x * blockDim.x;
    for (int i = blockIdx.x * blockDim.x + threadIdx.x; i < TOT; i += stride) {
        const float* src;
        __nv_bfloat16* dst;
        int off;
        if (i < ACT)          { src = hidden; dst = g_hb; off = i; }
        else if (i < 2 * ACT) { src = cross;  dst = g_cb; off = i - ACT; }
        else {
            const int t = i - 2 * ACT;
            const int w = t >> 18;
            off = t & (WV - 1);
            src = (w == 0) ? wq : (w == 1) ? wk : (w == 2) ? wv : (w == 3) ? wo : wg;
            dst = g_w5 + (size_t)w * (DIM * DIM);
        }
        const int idx = off * 4;
        float4 f = *reinterpret_cast<const float4*>(src + idx);
        __nv_bfloat162 lo, hi;
        lo.x = __float2bfloat16(f.x); lo.y = __float2bfloat16(f.y);
        hi.x = __float2bfloat16(f.z); hi.y = __float2bfloat16(f.w);
        *reinterpret_cast<__nv_bfloat162*>(dst + idx)     = lo;
        *reinterpret_cast<__nv_bfloat162*>(dst + idx + 2) = hi;
    }
}

// ---------------- bf16 GEMM body: C[M,N] = A[M,K] @ W[N,K]^T + bias, bf16 out -----
// 128x64x64 tiles, 3 CTAs/SM, 8 warps as 4m x 2n (warp tile 32x32).
DEVI void gemm_body(int bx, int by,
                    const __nv_bfloat16* __restrict__ A,
                    const __nv_bfloat16* __restrict__ W,
                    const float* __restrict__ bias,
                    __nv_bfloat16* __restrict__ Cout) {
    extern __shared__ char dsm[];
    const uint32_t sb = ((uint32_t)__cvta_generic_to_shared(dsm) + 127) & ~127u;
    const int tid  = threadIdx.x;
    const int lane = tid & 31, wid = tid >> 5;
    const int wm = wid >> 1, wn = wid & 1;     // 4m x 2n
    const int bm = by * BM, bn = bx * BN;

    float acc[2][4][4];
#pragma unroll
    for (int mt = 0; mt < 2; mt++)
#pragma unroll
        for (int nt = 0; nt < 4; nt++)
#pragma unroll
            for (int i = 0; i < 4; i++) acc[mt][nt][i] = 0.f;

    auto stage = [&](int kt) {
        const uint32_t abase = sb + (kt % NST) * STAGE_BYTES;
#pragma unroll
        for (int s = 0; s < 6; s++) {              // 192 rows * 8 chunks / 256 thr
            const int i = tid + s * 256;
            const int r = i >> 3, c = i & 7;
            const __nv_bfloat16* src = (r < BM)
                ? A + (size_t)(bm + r) * DIM + kt * BK + c * 8
                : W + (size_t)(bn + (r - BM)) * DIM + kt * BK + c * 8;
            cpasync16(abase + r * 128 + ((c ^ (r & 7)) * 16), src);
        }
        asm volatile("cp.async.commit_group;" ::: "memory");
    };

    stage(0);
    stage(1);
    for (int kt = 0; kt < KT; kt++) {
        if (kt < KT - 1) asm volatile("cp.async.wait_group 1;" ::: "memory");
        else             asm volatile("cp.async.wait_group 0;" ::: "memory");
        __syncthreads();
        if (kt + 2 < KT) stage(kt + 2);
        const uint32_t abase = sb + (kt % NST) * STAGE_BYTES;
        const uint32_t bbase = abase + BM * 128;
#pragma unroll
        for (int ks = 0; ks < BK / 16; ks++) {
            uint32_t af[2][4], bf[4][2];
#pragma unroll
            for (int mt = 0; mt < 2; mt++) {
                const int row = wm * 32 + mt * 16 + (lane & 15);
                const int c16 = ks * 2 + (lane >> 4);
                ldmx4(af[mt], abase + row * 128 + ((c16 ^ (row & 7)) * 16));
            }
#pragma unroll
            for (int j = 0; j < 2; j++) {
                // x4 covering nt=2j and 2j+1 (16 B-rows)
                const int row = wn * 32 + j * 16 + ((lane >> 4) & 1) * 8 + (lane & 7);
                const int c16 = ks * 2 + ((lane >> 3) & 1);
                uint32_t r[4];
                ldmx4(r, bbase + row * 128 + ((c16 ^ (row & 7)) * 16));
                bf[2 * j][0]     = r[0]; bf[2 * j][1]     = r[1];
                bf[2 * j + 1][0] = r[2]; bf[2 * j + 1][1] = r[3];
            }
#pragma unroll
            for (int mt = 0; mt < 2; mt++)
#pragma unroll
                for (int nt = 0; nt < 4; nt++)
                    mma16816(acc[mt][nt], af[mt], bf[nt]);
        }
    }

#pragma unroll
    for (int mt = 0; mt < 2; mt++) {
        const int row0 = bm + wm * 32 + mt * 16 + (lane >> 2);
#pragma unroll
        for (int nt = 0; nt < 4; nt++) {
            const int col = bn + wn * 32 + nt * 8 + (lane & 3) * 2;
            const float b0 = bias[col], b1 = bias[col + 1];
            *reinterpret_cast<uint32_t*>(Cout + (size_t)row0 * DIM + col) =
                pack_bf16(acc[mt][nt][0] + b0, acc[mt][nt][1] + b1);
            *reinterpret_cast<uint32_t*>(Cout + (size_t)(row0 + 8) * DIM + col) =
                pack_bf16(acc[mt][nt][2] + b0, acc[mt][nt][3] + b1);
        }
    }
}

// plain GEMM (O-projection): grid (16, 64)
__global__ __launch_bounds__(256, 3)
void gemm_kernel(const __nv_bfloat16* __restrict__ A,
                 const __nv_bfloat16* __restrict__ W,
                 const float* __restrict__ bias,
                 __nv_bfloat16* __restrict__ Cout) {
    gemm_body(blockIdx.x, blockIdx.y, A, W, bias, Cout);
}

// fused Q/K/V/gate GEMM: grid (64, 64); segment from blockIdx.x>>4
__global__ __launch_bounds__(256, 3)
void gemm_qkvg_kernel(const __nv_bfloat16* __restrict__ hb,
                      const __nv_bfloat16* __restrict__ cb,
                      const __nv_bfloat16* __restrict__ w5,
                      const float* __restrict__ bq, const float* __restrict__ bk,
                      const float* __restrict__ bv, const float* __restrict__ bg,
                      __nv_bfloat16* __restrict__ q, __nv_bfloat16* __restrict__ k,
                      __nv_bfloat16* __restrict__ v, __nv_bfloat16* __restrict__ gate) {
    const int seg = blockIdx.x >> 4;       // 0:Q 1:K 2:V 3:gate
    const int bx  = blockIdx.x & 15;
    const __nv_bfloat16* A = (seg == 1 || seg == 2) ? cb : hb;
    const int widx = (seg == 3) ? 4 : seg; // gate uses Wg at slot 4
    const __nv_bfloat16* W = w5 + (size_t)widx * DIM * DIM;
    const float* bias = (seg == 0) ? bq : (seg == 1) ? bk : (seg == 2) ? bv : bg;
    __nv_bfloat16* out = (seg == 0) ? q : (seg == 1) ? k : (seg == 2) ? v : gate;
    gemm_body(bx, blockIdx.y, A, W, bias, out);
}

// ---------------- banded attention (R10 verified) ----------------
__global__ __launch_bounds__(128, 4)
void attn_kernel(const __nv_bfloat16* __restrict__ Q,
                 const __nv_bfloat16* __restrict__ K,
                 const __nv_bfloat16* __restrict__ V,
                 __nv_bfloat16* __restrict__ Out) {
    extern __shared__ char smem[];
    char* Ks = smem;             // 192 rows * 128B
    char* Vs = smem + 24576;     // 192 rows * 128B
    const int b = blockIdx.x >> 4, h = blockIdx.x & 15;
    const int qt = blockIdx.y;
    const int tid = threadIdx.x, lane = tid & 31, wid = tid >> 5;
    const int k0 = qt * 64 - 64;
    const size_t base = ((size_t)b * SEQ) * DIM + h * HDIM;

    {
        const __nv_bfloat16* Kb = K + base;
        const __nv_bfloat16* Vb = V + base;
        for (int c = tid; c < 192 * 8; c += 128) {
            const int row = c >> 3, ch = c & 7;
            const int j = k0 + row;
            const bool ok = (j >= 0) && (j < SEQ);
            const int js = ok ? j : 0;
            const int sz = ok ? 16 : 0;
            const int sw = (ch ^ (row & 7)) * 16;
            cpasync16z((uint32_t)__cvta_generic_to_shared(Ks + row * 128 + sw),
                       reinterpret_cast<const char*>(Kb + (size_t)js * DIM) + ch * 16, sz);
            cpasync16z((uint32_t)__cvta_generic_to_shared(Vs + row * 128 + sw),
                       reinterpret_cast<const char*>(Vb + (size_t)js * DIM) + ch * 16, sz);
        }
        asm volatile("cp.async.commit_group;" ::: "memory");
    }

    uint32_t qf[4][4];
    const int wrow0 = wid * 16 + (lane >> 2);
    const int qr = qt * 64 + wrow0;
    {
        const __nv_bfloat16* q0 = Q + base + (size_t)qr * DIM;
        const __nv_bfloat16* q8 = Q + base + (size_t)(qr + 8) * DIM;
#pragma unroll
        for (int kt = 0; kt < 4; kt++) {
            const int c0 = kt * 16 + (lane & 3) * 2;
            qf[kt][0] = *reinterpret_cast<const uint32_t*>(q0 + c0);
            qf[kt][1] = *reinterpret_cast<const uint32_t*>(q8 + c0);
            qf[kt][2] = *reinterpret_cast<const uint32_t*>(q0 + c0 + 8);
            qf[kt][3] = *reinterpret_cast<const uint32_t*>(q8 + c0 + 8);
        }
    }
    asm volatile("cp.async.wait_group 0;" ::: "memory");
    __syncthreads();

    float sc[24][4];
#pragma unroll
    for (int nt = 0; nt < 24; nt++)
#pragma unroll
        for (int i = 0; i < 4; i++) sc[nt][i] = 0.f;
#pragma unroll
    for (int kt = 0; kt < 4; kt++) {
#pragma unroll
        for (int nt = 0; nt < 24; nt++) {
            uint32_t kb[2];
            const int krow = nt * 8 + (lane & 7);
            const int ch = kt * 2 + ((lane >> 3) & 1);
            ldmx2(kb, (uint32_t)__cvta_generic_to_shared(Ks + krow * 128 + (ch ^ (krow & 7)) * 16));
            mma16816(sc[nt], qf[kt], kb);
        }
    }

    const int lo0 = max(wrow0, -k0), hi0 = min(wrow0 + 128, 511 - k0);
    const int lo1 = max(wrow0 + 8, -k0), hi1 = min(wrow0 + 136, 511 - k0);
    const int colb = (lane & 3) * 2;
    float mx0 = -1e30f, mx1 = -1e30f;
#pragma unroll
    for (int nt = 0; nt < 24; nt++) {
#pragma unroll
        for (int c = 0; c < 2; c++) {
            const int idx = nt * 8 + colb + c;
            const float s0 = (idx >= lo0 && idx <= hi0) ? sc[nt][c] * ATT_SCALE : -1e30f;
            const float s1 = (idx >= lo1 && idx <= hi1) ? sc[nt][c + 2] * ATT_SCALE : -1e30f;
            sc[nt][c] = s0; sc[nt][c + 2] = s1;
            mx0 = fmaxf(mx0, s0); mx1 = fmaxf(mx1, s1);
        }
    }
    mx0 = fmaxf(mx0, __shfl_xor_sync(0xffffffffu, mx0, 1));
    mx0 = fmaxf(mx0, __shfl_xor_sync(0xffffffffu, mx0, 2));
    mx1 = fmaxf(mx1, __shfl_xor_sync(0xffffffffu, mx1, 1));
    mx1 = fmaxf(mx1, __shfl_xor_sync(0xffffffffu, mx1, 2));

    uint32_t pp[24][2];
    float l0 = 0.f, l1 = 0.f;
#pragma unroll
    for (int nt = 0; nt < 24; nt++) {
        const float p0 = __expf(sc[nt][0] - mx0);
        const float p1 = __expf(sc[nt][1] - mx0);
        const float p2 = __expf(sc[nt][2] - mx1);
        const float p3 = __expf(sc[nt][3] - mx1);
        l0 += p0 + p1; l1 += p2 + p3;
        pp[nt][0] = pack_bf16(p0, p1);
        pp[nt][1] = pack_bf16(p2, p3);
    }
    l0 += __shfl_xor_sync(0xffffffffu, l0, 1);
    l0 += __shfl_xor_sync(0xffffffffu, l0, 2);
    l1 += __shfl_xor_sync(0xffffffffu, l1, 1);
    l1 += __shfl_xor_sync(0xffffffffu, l1, 2);

    float oacc[8][4];
#pragma unroll
    for (int dt = 0; dt < 8; dt++)
#pragma unroll
        for (int i = 0; i < 4; i++) oacc[dt][i] = 0.f;
#pragma unroll
    for (int jt = 0; jt < 12; jt++) {
        const uint32_t pa[4] = {pp[2 * jt][0], pp[2 * jt][1],
                                pp[2 * jt + 1][0], pp[2 * jt + 1][1]};
        const int vrow = jt * 16 + (lane & 15);
#pragma unroll
        for (int dt = 0; dt < 8; dt++) {
            uint32_t vb[2];
            ldmx2t(vb, (uint32_t)__cvta_generic_to_shared(Vs + vrow * 128 + (dt ^ (vrow & 7)) * 16));
            mma16816(oacc[dt], pa, vb);
        }
    }

    const float i0 = 1.f / l0, i1 = 1.f / l1;
    __nv_bfloat16* ob = Out + base;
#pragma unroll
    for (int dt = 0; dt < 8; dt++) {
        const int col = dt * 8 + (lane & 3) * 2;
        *reinterpret_cast<uint32_t*>(ob + (size_t)qr * DIM + col) =
            pack_bf16(oacc[dt][0] * i0, oacc[dt][1] * i0);
        *reinterpret_cast<uint32_t*>(ob + (size_t)(qr + 8) * DIM + col) =
            pack_bf16(oacc[dt][2] * i1, oacc[dt][3] * i1);
    }
}

// ---------------- fused gate * attn, blend, LayerNorm (bf16 gate/yo) --------------
__global__ __launch_bounds__(256)
void final_kernel(const float* __restrict__ hid, const __nv_bfloat16* __restrict__ gate,
                  const __nv_bfloat16* __restrict__ yo, const float* __restrict__ gamma,
                  const float* __restrict__ beta, float* __restrict__ out) {
    const int row = blockIdx.x;
    const int tid = threadIdx.x;
    const size_t off = (size_t)row * DIM + tid * 4;
    const float4 hv = *reinterpret_cast<const float4*>(hid + off);
    const uint2 g2 = *reinterpret_cast<const uint2*>(gate + off);
    const uint2 y2 = *reinterpret_cast<const uint2*>(yo + off);
    const __nv_bfloat162 ga = *reinterpret_cast<const __nv_bfloat162*>(&g2.x);
    const __nv_bfloat162 gb = *reinterpret_cast<const __nv_bfloat162*>(&g2.y);
    const __nv_bfloat162 ya = *reinterpret_cast<const __nv_bfloat162*>(&y2.x);
    const __nv_bfloat162 yb = *reinterpret_cast<const __nv_bfloat162*>(&y2.y);
    const float gv[4] = {__bfloat162float(ga.x), __bfloat162float(ga.y),
                         __bfloat162float(gb.x), __bfloat162float(gb.y)};
    const float yv[4] = {__bfloat162float(ya.x), __bfloat162float(ya.y),
                         __bfloat162float(yb.x), __bfloat162float(yb.y)};
    const float hvv[4] = {hv.x, hv.y, hv.z, hv.w};
    float y[4];
#pragma unroll
    for (int i = 0; i < 4; i++)
        y[i] = 0.5f * hvv[i] + 0.5f * yv[i] / (1.f + __expf(-gv[i]));
    float s = y[0] + y[1] + y[2] + y[3];
    float s2 = y[0] * y[0] + y[1] * y[1] + y[2] * y[2] + y[3] * y[3];
#pragma unroll
    for (int o = 16; o > 0; o >>= 1) {
        s  += __shfl_xor_sync(0xffffffffu, s, o);
        s2 += __shfl_xor_sync(0xffffffffu, s2, o);
    }
    __shared__ float rs[8], rs2[8];
    if ((tid & 31) == 0) { rs[tid >> 5] = s; rs2[tid >> 5] = s2; }
    __syncthreads();
    float ts = 0.f, ts2 = 0.f;
#pragma unroll
    for (int w = 0; w < 8; w++) { ts += rs[w]; ts2 += rs2[w]; }
    const float mean = ts * (1.f / DIM);
    const float var = ts2 * (1.f / DIM) - mean * mean;
    const float rstd = rsqrtf(var + 1e-5f);
    const float4 gm = *reinterpret_cast<const float4*>(gamma + tid * 4);
    const float4 bt = *reinterpret_cast<const float4*>(beta + tid * 4);
    float4 o4;
    o4.x = (y[0] - mean) * rstd * gm.x + bt.x;
    o4.y = (y[1] - mean) * rstd * gm.y + bt.y;
    o4.z = (y[2] - mean) * rstd * gm.z + bt.z;
    o4.w = (y[3] - mean) * rstd * gm.w + bt.w;
    *reinterpret_cast<float4*>(out + off) = o4;
}

// ---------------- launch ----------------
extern "C" void kernel_launch(void* const* d_in, const int* in_sizes, int n_in,
                              void* d_out, int out_size) {
    (void)in_sizes; (void)n_in; (void)out_size;
    const float* hidden = (const float*)d_in[0];
    const float* cross  = (const float*)d_in[1];
    const float* Wq = (const float*)d_in[2];  const float* bq = (const float*)d_in[3];
    const float* Wk = (const float*)d_in[4];  const float* bk = (const float*)d_in[5];
    const float* Wv = (const float*)d_in[6];  const float* bv = (const float*)d_in[7];
    const float* Wo = (const float*)d_in[8];  const float* bo = (const float*)d_in[9];
    const float* Wg = (const float*)d_in[10]; const float* bg = (const float*)d_in[11];
    const float* gamma = (const float*)d_in[12];
    const float* beta  = (const float*)d_in[13];

    __nv_bfloat16 *hb, *cb, *w5, *q, *k, *v, *at, *gate, *yo;
    cudaGetSymbolAddress((void**)&hb, g_hb);
    cudaGetSymbolAddress((void**)&cb, g_cb);
    cudaGetSymbolAddress((void**)&w5, g_w5);
    cudaGetSymbolAddress((void**)&q,  g_q);
    cudaGetSymbolAddress((void**)&k,  g_k);
    cudaGetSymbolAddress((void**)&v,  g_v);
    cudaGetSymbolAddress((void**)&at, g_attn);
    cudaGetSymbolAddress((void**)&gate, g_gate);
    cudaGetSymbolAddress((void**)&yo,   g_yo);

    cudaFuncSetAttribute(gemm_kernel,
                         cudaFuncAttributeMaxDynamicSharedMemorySize, GEMM_SMEM);
    cudaFuncSetAttribute(gemm_qkvg_kernel,
                         cudaFuncAttributeMaxDynamicSharedMemorySize, GEMM_SMEM);

    cvt_all_kernel<<<2752, 256>>>(hidden, cross, Wq, Wk, Wv, Wo, Wg);

    const __nv_bfloat16* wo = w5 + 3 * (size_t)DIM * DIM;

    // fused Q/K/V/gate: grid (64, 64) = 4096 CTAs (4 segs x 16 n-tiles x 64 m-tiles)
    gemm_qkvg_kernel<<<dim3(64, 64), 256, GEMM_SMEM>>>(hb, cb, w5,
                                                       bq, bk, bv, bg,
                                                       q, k, v, gate);

    attn_kernel<<<dim3(BATCH * NH, SEQ / 64), 128, 49152>>>(q, k, v, at);

    gemm_kernel<<<dim3(16, 64), 256, GEMM_SMEM>>>(at, wo, bo, yo);

    final_kernel<<<MROWS, 256>>>(hidden, gate, yo, gamma, beta, (float*)d_out);
}

// round 12
// speedup vs baseline: 1.0080x; 1.0080x over previous
#include <cuda_runtime.h>
#include <cuda_bf16.h>
#include <cstdint>
#include <cstddef>

#define DEVI __device__ __forceinline__

namespace {
constexpr int BATCH = 16, SEQ = 512, DIM = 1024, NH = 16, HDIM = 64;
constexpr int MROWS = BATCH * SEQ;      // 8192
constexpr float ATT_SCALE = 0.125f;     // 1/sqrt(64)
// FP8 GEMM: tile 128x128, K-chunk 128 fp8 = 128B row (same XOR swizzle)
constexpr int BM = 128, BN = 128, BK = 128;
constexpr int KT = DIM / BK;                 // 8
constexpr int NST = 3;
constexpr int STAGE_BYTES = (BM + BN) * 128; // 32768
constexpr int GEMM_SMEM = NST * STAGE_BYTES + 256;
constexpr float WSCALE = 1024.f;             // weight fp8 scale
constexpr float ASCALE = 256.f;              // attn-out fp8 scale
constexpr float OS_QKVG = 1.f / 1024.f;
constexpr float OS_O    = 1.f / (1024.f * 256.f);
}

// ---------------- scratch (device globals; no allocation allowed) ----------------
__device__ uint8_t g_h8[MROWS * DIM];           // hidden fp8
__device__ uint8_t g_c8[MROWS * DIM];           // cross fp8
__device__ uint8_t g_w8[5 * DIM * DIM];         // Wq,Wk,Wv,Wo,Wg fp8 x1024
__device__ __nv_bfloat16 g_q[MROWS * DIM];
__device__ __nv_bfloat16 g_k[MROWS * DIM];
__device__ __nv_bfloat16 g_v[MROWS * DIM];
__device__ uint8_t g_at8[MROWS * DIM];          // attn out fp8 x256
__device__ __nv_bfloat16 g_gate[MROWS * DIM];
__device__ __nv_bfloat16 g_yo[MROWS * DIM];

// ---------------- small helpers ----------------
DEVI uint32_t pack_bf16(float a, float b) {
    __nv_bfloat162 t;
    t.x = __float2bfloat16(a);
    t.y = __float2bfloat16(b);
    return *reinterpret_cast<uint32_t*>(&t);
}
// pack (lo, hi) floats to e4m3x2; lo lands in low byte (lower address)
DEVI uint16_t pack_e4m3(float lo, float hi) {
    uint16_t r;
    asm("cvt.rn.satfinite.e4m3x2.f32 %0, %1, %2;" : "=h"(r) : "f"(hi), "f"(lo));
    return r;
}
DEVI void mma16816(float* c, const uint32_t* a, const uint32_t* b) {
    asm volatile(
        "mma.sync.aligned.m16n8k16.row.col.f32.bf16.bf16.f32 "
        "{%0,%1,%2,%3}, {%4,%5,%6,%7}, {%8,%9}, {%0,%1,%2,%3};"
        : "+f"(c[0]), "+f"(c[1]), "+f"(c[2]), "+f"(c[3])
        : "r"(a[0]), "r"(a[1]), "r"(a[2]), "r"(a[3]), "r"(b[0]), "r"(b[1]));
}
DEVI void mma16832f8(float* c, const uint32_t* a, const uint32_t* b) {
    asm volatile(
        "mma.sync.aligned.m16n8k32.row.col.f32.e4m3.e4m3.f32 "
        "{%0,%1,%2,%3}, {%4,%5,%6,%7}, {%8,%9}, {%0,%1,%2,%3};"
        : "+f"(c[0]), "+f"(c[1]), "+f"(c[2]), "+f"(c[3])
        : "r"(a[0]), "r"(a[1]), "r"(a[2]), "r"(a[3]), "r"(b[0]), "r"(b[1]));
}
DEVI void ldmx4(uint32_t* r, uint32_t addr) {
    asm volatile("ldmatrix.sync.aligned.m8n8.x4.shared.b16 {%0,%1,%2,%3}, [%4];"
                 : "=r"(r[0]), "=r"(r[1]), "=r"(r[2]), "=r"(r[3]) : "r"(addr));
}
DEVI void ldmx2(uint32_t* r, uint32_t addr) {
    asm volatile("ldmatrix.sync.aligned.m8n8.x2.shared.b16 {%0,%1}, [%2];"
                 : "=r"(r[0]), "=r"(r[1]) : "r"(addr));
}
DEVI void ldmx2t(uint32_t* r, uint32_t addr) {
    asm volatile("ldmatrix.sync.aligned.m8n8.x2.trans.shared.b16 {%0,%1}, [%2];"
                 : "=r"(r[0]), "=r"(r[1]) : "r"(addr));
}
DEVI void cpasync16(uint32_t dst, const void* src) {
    asm volatile("cp.async.cg.shared.global [%0], [%1], 16;" :: "r"(dst), "l"(src));
}
DEVI void cpasync16z(uint32_t dst, const void* src, int srcsize) {
    asm volatile("cp.async.cg.shared.global [%0], [%1], 16, %2;"
                 :: "r"(dst), "l"(src), "r"(srcsize));
}

// ---------------- fused fp32 -> fp8 conversion (activations + 5 weights x1024) ----
__global__ void cvt_all_kernel(const float* __restrict__ hidden, const float* __restrict__ cross,
                               const float* __restrict__ wq, const float* __restrict__ wk,
                               const float* __restrict__ wv, const float* __restrict__ wo,
                               const float* __restrict__ wg) {
    constexpr int ACT = MROWS * DIM / 4;   // 2097152 vec4
    constexpr int WV  = DIM * DIM / 4;     // 262144 vec4 (2^18)
    constexpr int TOT = 2 * ACT + 5 * WV;
    const int stride = gridDim.x * blockDim.x;
    for (int i = blockIdx.x * blockDim.x + threadIdx.x; i < TOT; i += stride) {
        const float* src;
        uint8_t* dst;
        int off;
        float scale;
        if (i < ACT)          { src = hidden; dst = g_h8; off = i; scale = 1.f; }
        else if (i < 2 * ACT) { src = cross;  dst = g_c8; off = i - ACT; scale = 1.f; }
        else {
            const int t = i - 2 * ACT;
            const int w = t >> 18;
            off = t & (WV - 1);
            src = (w == 0) ? wq : (w == 1) ? wk : (w == 2) ? wv : (w == 3) ? wo : wg;
            dst = g_w8 + (size_t)w * (DIM * DIM);
            scale = WSCALE;
        }
        const int idx = off * 4;
        float4 f = *reinterpret_cast<const float4*>(src + idx);
        const uint16_t p0 = pack_e4m3(f.x * scale, f.y * scale);
        const uint16_t p1 = pack_e4m3(f.z * scale, f.w * scale);
        *reinterpret_cast<uint32_t*>(dst + idx) = (uint32_t)p0 | ((uint32_t)p1 << 16);
    }
}

// ---------------- FP8 GEMM body: C[M,N] = (A @ W^T) * oscale + bias, bf16 out -----
// 128x128x(K=1024) tiles, KT=8 chunks of 128 fp8, 8 warps 2m x 4n (warp 64x32).
DEVI void gemm_body(int bx, int by,
                    const uint8_t* __restrict__ A,
                    const uint8_t* __restrict__ W,
                    const float* __restrict__ bias, float oscale,
                    __nv_bfloat16* __restrict__ Cout) {
    extern __shared__ char dsm[];
    const uint32_t sb = ((uint32_t)__cvta_generic_to_shared(dsm) + 127) & ~127u;
    const int tid  = threadIdx.x;
    const int lane = tid & 31, wid = tid >> 5;
    const int wm = wid >> 2, wn = wid & 3;
    const int bm = by * BM, bn = bx * BN;

    float acc[4][4][4];
#pragma unroll
    for (int mt = 0; mt < 4; mt++)
#pragma unroll
        for (int nt = 0; nt < 4; nt++)
#pragma unroll
            for (int i = 0; i < 4; i++) acc[mt][nt][i] = 0.f;

    auto stage = [&](int kt) {
        const uint32_t base = sb + (kt % NST) * STAGE_BYTES;
#pragma unroll
        for (int s = 0; s < 8; s++) {              // 256 rows * 8 chunks / 256 thr
            const int i = tid + s * 256;
            const int r = i >> 3, c = i & 7;
            const uint8_t* src = (r < BM)
                ? A + (size_t)(bm + r) * DIM + kt * BK + c * 16
                : W + (size_t)(bn + (r - BM)) * DIM + kt * BK + c * 16;
            cpasync16(base + r * 128 + ((c ^ (r & 7)) * 16), src);
        }
        asm volatile("cp.async.commit_group;" ::: "memory");
    };

    stage(0);
    stage(1);
    for (int kt = 0; kt < KT; kt++) {
        if (kt < KT - 1) asm volatile("cp.async.wait_group 1;" ::: "memory");
        else             asm volatile("cp.async.wait_group 0;" ::: "memory");
        __syncthreads();
        if (kt + 2 < KT) stage(kt + 2);
        const uint32_t abase = sb + (kt % NST) * STAGE_BYTES;
        const uint32_t bbase = abase + BM * 128;
#pragma unroll
        for (int ks = 0; ks < BK / 32; ks++) {     // 4 k32-slices per 128B chunk... (2 chunks each)
            uint32_t af[4][4], bf[4][2];
#pragma unroll
            for (int mt = 0; mt < 4; mt++) {
                const int row = wm * 64 + mt * 16 + (lane & 15);
                const int c16 = ks * 2 + (lane >> 4);   // 32B slice = 2 x 16B chunks
                ldmx4(af[mt], abase + row * 128 + ((c16 ^ (row & 7)) * 16));
            }
#pragma unroll
            for (int j = 0; j < 2; j++) {
                const int row = wn * 32 + j * 16 + ((lane >> 4) & 1) * 8 + (lane & 7);
                const int c16 = ks * 2 + ((lane >> 3) & 1);
                uint32_t r[4];
                ldmx4(r, bbase + row * 128 + ((c16 ^ (row & 7)) * 16));
                bf[2 * j][0]     = r[0]; bf[2 * j][1]     = r[1];
                bf[2 * j + 1][0] = r[2]; bf[2 * j + 1][1] = r[3];
            }
#pragma unroll
            for (int mt = 0; mt < 4; mt++)
#pragma unroll
                for (int nt = 0; nt < 4; nt++)
                    mma16832f8(acc[mt][nt], af[mt], bf[nt]);
        }
    }

#pragma unroll
    for (int mt = 0; mt < 4; mt++) {
        const int row0 = bm + wm * 64 + mt * 16 + (lane >> 2);
#pragma unroll
        for (int nt = 0; nt < 4; nt++) {
            const int col = bn + wn * 32 + nt * 8 + (lane & 3) * 2;
            const float b0 = bias[col], b1 = bias[col + 1];
            *reinterpret_cast<uint32_t*>(Cout + (size_t)row0 * DIM + col) =
                pack_bf16(acc[mt][nt][0] * oscale + b0, acc[mt][nt][1] * oscale + b1);
            *reinterpret_cast<uint32_t*>(Cout + (size_t)(row0 + 8) * DIM + col) =
                pack_bf16(acc[mt][nt][2] * oscale + b0, acc[mt][nt][3] * oscale + b1);
        }
    }
}

// plain FP8 GEMM (O-projection): grid (8, 64)
__global__ __launch_bounds__(256, 2)
void gemm_kernel(const uint8_t* __restrict__ A,
                 const uint8_t* __restrict__ W,
                 const float* __restrict__ bias, float oscale,
                 __nv_bfloat16* __restrict__ Cout) {
    gemm_body(blockIdx.x, blockIdx.y, A, W, bias, oscale, Cout);
}

// fused Q/K/V/gate FP8 GEMM: grid (32, 64); segment from blockIdx.x>>3
__global__ __launch_bounds__(256, 2)
void gemm_qkvg_kernel(const uint8_t* __restrict__ h8,
                      const uint8_t* __restrict__ c8,
                      const uint8_t* __restrict__ w8,
                      const float* __restrict__ bq, const float* __restrict__ bk,
                      const float* __restrict__ bv, const float* __restrict__ bg,
                      __nv_bfloat16* __restrict__ q, __nv_bfloat16* __restrict__ k,
                      __nv_bfloat16* __restrict__ v, __nv_bfloat16* __restrict__ gate) {
    const int seg = blockIdx.x >> 3;       // 0:Q 1:K 2:V 3:gate
    const int bx  = blockIdx.x & 7;
    const uint8_t* A = (seg == 1 || seg == 2) ? c8 : h8;
    const int widx = (seg == 3) ? 4 : seg;
    const uint8_t* W = w8 + (size_t)widx * DIM * DIM;
    const float* bias = (seg == 0) ? bq : (seg == 1) ? bk : (seg == 2) ? bv : bg;
    __nv_bfloat16* out = (seg == 0) ? q : (seg == 1) ? k : (seg == 2) ? v : gate;
    gemm_body(bx, blockIdx.y, A, W, bias, OS_QKVG, out);
}

// ---------------- banded attention (R10 verified; out -> fp8 x256) ----------------
__global__ __launch_bounds__(128, 4)
void attn_kernel(const __nv_bfloat16* __restrict__ Q,
                 const __nv_bfloat16* __restrict__ K,
                 const __nv_bfloat16* __restrict__ V,
                 uint8_t* __restrict__ Out) {
    extern __shared__ char smem[];
    char* Ks = smem;             // 192 rows * 128B
    char* Vs = smem + 24576;     // 192 rows * 128B
    const int b = blockIdx.x >> 4, h = blockIdx.x & 15;
    const int qt = blockIdx.y;
    const int tid = threadIdx.x, lane = tid & 31, wid = tid >> 5;
    const int k0 = qt * 64 - 64;
    const size_t base = ((size_t)b * SEQ) * DIM + h * HDIM;

    {
        const __nv_bfloat16* Kb = K + base;
        const __nv_bfloat16* Vb = V + base;
        for (int c = tid; c < 192 * 8; c += 128) {
            const int row = c >> 3, ch = c & 7;
            const int j = k0 + row;
            const bool ok = (j >= 0) && (j < SEQ);
            const int js = ok ? j : 0;
            const int sz = ok ? 16 : 0;
            const int sw = (ch ^ (row & 7)) * 16;
            cpasync16z((uint32_t)__cvta_generic_to_shared(Ks + row * 128 + sw),
                       reinterpret_cast<const char*>(Kb + (size_t)js * DIM) + ch * 16, sz);
            cpasync16z((uint32_t)__cvta_generic_to_shared(Vs + row * 128 + sw),
                       reinterpret_cast<const char*>(Vb + (size_t)js * DIM) + ch * 16, sz);
        }
        asm volatile("cp.async.commit_group;" ::: "memory");
    }

    uint32_t qf[4][4];
    const int wrow0 = wid * 16 + (lane >> 2);
    const int qr = qt * 64 + wrow0;
    {
        const __nv_bfloat16* q0 = Q + base + (size_t)qr * DIM;
        const __nv_bfloat16* q8 = Q + base + (size_t)(qr + 8) * DIM;
#pragma unroll
        for (int kt = 0; kt < 4; kt++) {
            const int c0 = kt * 16 + (lane & 3) * 2;
            qf[kt][0] = *reinterpret_cast<const uint32_t*>(q0 + c0);
            qf[kt][1] = *reinterpret_cast<const uint32_t*>(q8 + c0);
            qf[kt][2] = *reinterpret_cast<const uint32_t*>(q0 + c0 + 8);
            qf[kt][3] = *reinterpret_cast<const uint32_t*>(q8 + c0 + 8);
        }
    }
    asm volatile("cp.async.wait_group 0;" ::: "memory");
    __syncthreads();

    float sc[24][4];
#pragma unroll
    for (int nt = 0; nt < 24; nt++)
#pragma unroll
        for (int i = 0; i < 4; i++) sc[nt][i] = 0.f;
#pragma unroll
    for (int kt = 0; kt < 4; kt++) {
#pragma unroll
        for (int nt = 0; nt < 24; nt++) {
            uint32_t kb[2];
            const int krow = nt * 8 + (lane & 7);
            const int ch = kt * 2 + ((lane >> 3) & 1);
            ldmx2(kb, (uint32_t)__cvta_generic_to_shared(Ks + krow * 128 + (ch ^ (krow & 7)) * 16));
            mma16816(sc[nt], qf[kt], kb);
        }
    }

    const int lo0 = max(wrow0, -k0), hi0 = min(wrow0 + 128, 511 - k0);
    const int lo1 = max(wrow0 + 8, -k0), hi1 = min(wrow0 + 136, 511 - k0);
    const int colb = (lane & 3) * 2;
    float mx0 = -1e30f, mx1 = -1e30f;
#pragma unroll
    for (int nt = 0; nt < 24; nt++) {
#pragma unroll
        for (int c = 0; c < 2; c++) {
            const int idx = nt * 8 + colb + c;
            const float s0 = (idx >= lo0 && idx <= hi0) ? sc[nt][c] * ATT_SCALE : -1e30f;
            const float s1 = (idx >= lo1 && idx <= hi1) ? sc[nt][c + 2] * ATT_SCALE : -1e30f;
            sc[nt][c] = s0; sc[nt][c + 2] = s1;
            mx0 = fmaxf(mx0, s0); mx1 = fmaxf(mx1, s1);
        }
    }
    mx0 = fmaxf(mx0, __shfl_xor_sync(0xffffffffu, mx0, 1));
    mx0 = fmaxf(mx0, __shfl_xor_sync(0xffffffffu, mx0, 2));
    mx1 = fmaxf(mx1, __shfl_xor_sync(0xffffffffu, mx1, 1));
    mx1 = fmaxf(mx1, __shfl_xor_sync(0xffffffffu, mx1, 2));

    uint32_t pp[24][2];
    float l0 = 0.f, l1 = 0.f;
#pragma unroll
    for (int nt = 0; nt < 24; nt++) {
        const float p0 = __expf(sc[nt][0] - mx0);
        const float p1 = __expf(sc[nt][1] - mx0);
        const float p2 = __expf(sc[nt][2] - mx1);
        const float p3 = __expf(sc[nt][3] - mx1);
        l0 += p0 + p1; l1 += p2 + p3;
        pp[nt][0] = pack_bf16(p0, p1);
        pp[nt][1] = pack_bf16(p2, p3);
    }
    l0 += __shfl_xor_sync(0xffffffffu, l0, 1);
    l0 += __shfl_xor_sync(0xffffffffu, l0, 2);
    l1 += __shfl_xor_sync(0xffffffffu, l1, 1);
    l1 += __shfl_xor_sync(0xffffffffu, l1, 2);

    float oacc[8][4];
#pragma unroll
    for (int dt = 0; dt < 8; dt++)
#pragma unroll
        for (int i = 0; i < 4; i++) oacc[dt][i] = 0.f;
#pragma unroll
    for (int jt = 0; jt < 12; jt++) {
        const uint32_t pa[4] = {pp[2 * jt][0], pp[2 * jt][1],
                                pp[2 * jt + 1][0], pp[2 * jt + 1][1]};
        const int vrow = jt * 16 + (lane & 15);
#pragma unroll
        for (int dt = 0; dt < 8; dt++) {
            uint32_t vb[2];
            ldmx2t(vb, (uint32_t)__cvta_generic_to_shared(Vs + vrow * 128 + (dt ^ (vrow & 7)) * 16));
            mma16816(oacc[dt], pa, vb);
        }
    }

    const float i0 = ASCALE / l0, i1 = ASCALE / l1;   // fold fp8 scale into normalization
    uint8_t* ob = Out + base;
#pragma unroll
    for (int dt = 0; dt < 8; dt++) {
        const int col = dt * 8 + (lane & 3) * 2;
        *reinterpret_cast<uint16_t*>(ob + (size_t)qr * DIM + col) =
            pack_e4m3(oacc[dt][0] * i0, oacc[dt][1] * i0);
        *reinterpret_cast<uint16_t*>(ob + (size_t)(qr + 8) * DIM + col) =
            pack_e4m3(oacc[dt][2] * i1, oacc[dt][3] * i1);
    }
}

// ---------------- fused gate * attn, blend, LayerNorm (bf16 gate/yo) --------------
__global__ __launch_bounds__(256)
void final_kernel(const float* __restrict__ hid, const __nv_bfloat16* __restrict__ gate,
                  const __nv_bfloat16* __restrict__ yo, const float* __restrict__ gamma,
                  const float* __restrict__ beta, float* __restrict__ out) {
    const int row = blockIdx.x;
    const int tid = threadIdx.x;
    const size_t off = (size_t)row * DIM + tid * 4;
    const float4 hv = *reinterpret_cast<const float4*>(hid + off);
    const uint2 g2 = *reinterpret_cast<const uint2*>(gate + off);
    const uint2 y2 = *reinterpret_cast<const uint2*>(yo + off);
    const __nv_bfloat162 ga = *reinterpret_cast<const __nv_bfloat162*>(&g2.x);
    const __nv_bfloat162 gb = *reinterpret_cast<const __nv_bfloat162*>(&g2.y);
    const __nv_bfloat162 ya = *reinterpret_cast<const __nv_bfloat162*>(&y2.x);
    const __nv_bfloat162 yb = *reinterpret_cast<const __nv_bfloat162*>(&y2.y);
    const float gv[4] = {__bfloat162float(ga.x), __bfloat162float(ga.y),
                         __bfloat162float(gb.x), __bfloat162float(gb.y)};
    const float yv[4] = {__bfloat162float(ya.x), __bfloat162float(ya.y),
                         __bfloat162float(yb.x), __bfloat162float(yb.y)};
    const float hvv[4] = {hv.x, hv.y, hv.z, hv.w};
    float y[4];
#pragma unroll
    for (int i = 0; i < 4; i++)
        y[i] = 0.5f * hvv[i] + 0.5f * yv[i] / (1.f + __expf(-gv[i]));
    float s = y[0] + y[1] + y[2] + y[3];
    float s2 = y[0] * y[0] + y[1] * y[1] + y[2] * y[2] + y[3] * y[3];
#pragma unroll
    for (int o = 16; o > 0; o >>= 1) {
        s  += __shfl_xor_sync(0xffffffffu, s, o);
        s2 += __shfl_xor_sync(0xffffffffu, s2, o);
    }
    __shared__ float rs[8], rs2[8];
    if ((tid & 31) == 0) { rs[tid >> 5] = s; rs2[tid >> 5] = s2; }
    __syncthreads();
    float ts = 0.f, ts2 = 0.f;
#pragma unroll
    for (int w = 0; w < 8; w++) { ts += rs[w]; ts2 += rs2[w]; }
    const float mean = ts * (1.f / DIM);
    const float var = ts2 * (1.f / DIM) - mean * mean;
    const float rstd = rsqrtf(var + 1e-5f);
    const float4 gm = *reinterpret_cast<const float4*>(gamma + tid * 4);
    const float4 bt = *reinterpret_cast<const float4*>(beta + tid * 4);
    float4 o4;
    o4.x = (y[0] - mean) * rstd * gm.x + bt.x;
    o4.y = (y[1] - mean) * rstd * gm.y + bt.y;
    o4.z = (y[2] - mean) * rstd * gm.z + bt.z;
    o4.w = (y[3] - mean) * rstd * gm.w + bt.w;
    *reinterpret_cast<float4*>(out + off) = o4;
}

// ---------------- launch ----------------
extern "C" void kernel_launch(void* const* d_in, const int* in_sizes, int n_in,
                              void* d_out, int out_size) {
    (void)in_sizes; (void)n_in; (void)out_size;
    const float* hidden = (const float*)d_in[0];
    const float* cross  = (const float*)d_in[1];
    const float* Wq = (const float*)d_in[2];  const float* bq = (const float*)d_in[3];
    const float* Wk = (const float*)d_in[4];  const float* bk = (const float*)d_in[5];
    const float* Wv = (const float*)d_in[6];  const float* bv = (const float*)d_in[7];
    const float* Wo = (const float*)d_in[8];  const float* bo = (const float*)d_in[9];
    const float* Wg = (const float*)d_in[10]; const float* bg = (const float*)d_in[11];
    const float* gamma = (const float*)d_in[12];
    const float* beta  = (const float*)d_in[13];

    uint8_t *h8, *c8, *w8, *at8;
    __nv_bfloat16 *q, *k, *v, *gate, *yo;
    cudaGetSymbolAddress((void**)&h8, g_h8);
    cudaGetSymbolAddress((void**)&c8, g_c8);
    cudaGetSymbolAddress((void**)&w8, g_w8);
    cudaGetSymbolAddress((void**)&q,  g_q);
    cudaGetSymbolAddress((void**)&k,  g_k);
    cudaGetSymbolAddress((void**)&v,  g_v);
    cudaGetSymbolAddress((void**)&at8, g_at8);
    cudaGetSymbolAddress((void**)&gate, g_gate);
    cudaGetSymbolAddress((void**)&yo,   g_yo);

    cudaFuncSetAttribute(gemm_kernel,
                         cudaFuncAttributeMaxDynamicSharedMemorySize, GEMM_SMEM);
    cudaFuncSetAttribute(gemm_qkvg_kernel,
                         cudaFuncAttributeMaxDynamicSharedMemorySize, GEMM_SMEM);

    cvt_all_kernel<<<2752, 256>>>(hidden, cross, Wq, Wk, Wv, Wo, Wg);

    const uint8_t* wo8 = w8 + 3 * (size_t)DIM * DIM;

    // fused Q/K/V/gate: grid (32, 64) = 2048 CTAs (4 segs x 8 n-tiles x 64 m-tiles)
    gemm_qkvg_kernel<<<dim3(32, 64), 256, GEMM_SMEM>>>(h8, c8, w8,
                                                       bq, bk, bv, bg,
                                                       q, k, v, gate);

    attn_kernel<<<dim3(BATCH * NH, SEQ / 64), 128, 49152>>>(q, k, v, at8);

    gemm_kernel<<<dim3(8, 64), 256, GEMM_SMEM>>>(at8, wo8, bo, OS_O, yo);

    final_kernel<<<MROWS, 256>>>(hidden, gate, yo, gamma, beta, (float*)d_out);
}